// round 6
// baseline (speedup 1.0000x reference)
#include <cuda_runtime.h>
#include <cstdint>

// ---------------------------------------------------------------------------
// GraphSAGE (3x SAGEConv mean + linear head), N=50000, E=600000, 16->128->128->128->4
//   R4: multi-block scan (was 46us single-block), float4 l1, half-warp agg16,
//       GEMM re-tiled to 64x128 blocks (occ 5, ~single wave).
// ---------------------------------------------------------------------------

#define NN 50000
#define NE 600000

__device__ int   g_is64;
__device__ int   g_deg[NN];
__device__ int   g_off[NN + 1];
__device__ int   g_cur[NN];
__device__ int   g_bsum[64];
__device__ int   g_boff[64];
__device__ int   g_srcl[NE];
__device__ __align__(16) float g_agg16[NN * 16];
__device__ __align__(16) float g_agg[NN * 128];
__device__ __align__(16) float g_h1[NN * 128];
__device__ __align__(16) float g_h2[NN * 128];
__device__ __align__(16) float g_U[2 * 256 * 128];   // k-major [Wl|Wr] for layers 2,3

// ---------------- fp32x2 helpers ----------------
__device__ __forceinline__ unsigned long long pack2f(float a, float b) {
    unsigned long long r;
    asm("mov.b64 %0, {%1, %2};" : "=l"(r) : "f"(a), "f"(b));
    return r;
}
__device__ __forceinline__ void unpack2f(unsigned long long v, float& a, float& b) {
    asm("mov.b64 {%0, %1}, %2;" : "=f"(a), "=f"(b) : "l"(v));
}
__device__ __forceinline__ unsigned long long ffma2(unsigned long long a,
                                                    unsigned long long b,
                                                    unsigned long long c) {
    unsigned long long d;
    asm("fma.rn.f32x2 %0, %1, %2, %3;" : "=l"(d) : "l"(a), "l"(b), "l"(c));
    return d;
}

__device__ __forceinline__ int edge_val(const void* ei, long long idx, int is64) {
    if (is64) return (int)((const long long*)ei)[idx];
    return ((const int*)ei)[idx];
}

// ---------------- init: zero degrees + detect edge dtype ----------------
__global__ void init_k(const void* ei, int n) {
    int i = blockIdx.x * blockDim.x + threadIdx.x;
    if (i < n) g_deg[i] = 0;
    if (i == 0) {
        const int* p = (const int*)ei;
        int acc = 0;
        for (int j = 1; j < 256; j += 2) acc |= p[j];
        g_is64 = (acc == 0) ? 1 : 0;
    }
}

__global__ void count_k(const void* ei, int e) {
    int i = blockIdx.x * blockDim.x + threadIdx.x;
    if (i >= e) return;
    int is64 = g_is64;
    int d = edge_val(ei, (long long)e + i, is64);
    atomicAdd(&g_deg[d], 1);
}

// ---------------- multi-block exclusive scan of g_deg -> g_off ----------------
__global__ __launch_bounds__(1024) void partscan_k(int n) {
    __shared__ int wsum[32];
    int tid = threadIdx.x, lane = tid & 31, wid = tid >> 5;
    int i = blockIdx.x * 1024 + tid;
    int v = (i < n) ? g_deg[i] : 0;
    int xv = v;
#pragma unroll
    for (int o = 1; o < 32; o <<= 1) {
        int y = __shfl_up_sync(0xffffffffu, xv, o);
        if (lane >= o) xv += y;
    }
    if (lane == 31) wsum[wid] = xv;
    __syncthreads();
    if (wid == 0) {
        int wv = wsum[lane];
        int xw = wv;
#pragma unroll
        for (int o = 1; o < 32; o <<= 1) {
            int y = __shfl_up_sync(0xffffffffu, xw, o);
            if (lane >= o) xw += y;
        }
        wsum[lane] = xw - wv;   // exclusive warp offsets
    }
    __syncthreads();
    int incl = xv + wsum[wid];
    if (i < n) g_off[i] = incl - v;            // block-local exclusive
    if (tid == 1023) g_bsum[blockIdx.x] = incl;
}

__global__ void bscan_k(int nb, int n) {       // 1 block, 64 threads
    __shared__ int ws[2];
    int t = threadIdx.x, lane = t & 31, w = t >> 5;
    int v = (t < nb) ? g_bsum[t] : 0;
    int x = v;
#pragma unroll
    for (int o = 1; o < 32; o <<= 1) {
        int y = __shfl_up_sync(0xffffffffu, x, o);
        if (lane >= o) x += y;
    }
    if (lane == 31) ws[w] = x;
    __syncthreads();
    if (w == 1) x += ws[0];
    g_boff[t] = x - v;                         // exclusive block offsets
    if (t == 63) g_off[n] = x;                 // grand total
}

__global__ void addoff_k(int n) {
    int i = blockIdx.x * blockDim.x + threadIdx.x;
    if (i < n) {
        int o = g_off[i] + g_boff[i >> 10];
        g_off[i] = o;
        g_cur[i] = o;
    }
}

__global__ void fill_k(const void* ei, int e) {
    int i = blockIdx.x * blockDim.x + threadIdx.x;
    if (i >= e) return;
    int is64 = g_is64;
    int s = edge_val(ei, i, is64);
    int d = edge_val(ei, (long long)e + i, is64);
    int p = atomicAdd(&g_cur[d], 1);
    g_srcl[p] = s;
}

// ---------------- weight prep: U[k][o] = k<128 ? Wl[o][k] : Wr[o][k-128] ----------------
__global__ void prepU_k(const float* __restrict__ Wl2, const float* __restrict__ Wr2,
                        const float* __restrict__ Wl3, const float* __restrict__ Wr3) {
    int idx = blockIdx.x * blockDim.x + threadIdx.x;   // 0 .. 65535
    int layer = idx >> 15;
    int r = idx & 32767;
    int k = r >> 7;
    int o = r & 127;
    const float* Wl = layer ? Wl3 : Wl2;
    const float* Wr = layer ? Wr3 : Wr2;
    float v = (k < 128) ? Wl[o * 128 + k] : Wr[o * 128 + (k - 128)];
    g_U[layer * 32768 + k * 128 + o] = v;
}

// ---------------- layer-1 aggregation: half-warp per node (16-dim mean) ----------------
__global__ __launch_bounds__(256) void agg16_k(const float* __restrict__ x, int n) {
    int hw = (blockIdx.x * blockDim.x + threadIdx.x) >> 4;   // half-warp = node
    if (hw >= n) return;
    int lane = threadIdx.x & 15;
    int e0 = g_off[hw], e1 = g_off[hw + 1];
    float s = 0.f;
    int e = e0;
    for (; e + 1 < e1; e += 2) {
        int s0 = g_srcl[e], s1 = g_srcl[e + 1];
        s += x[s0 * 16 + lane] + x[s1 * 16 + lane];
    }
    if (e < e1) s += x[g_srcl[e] * 16 + lane];
    float inv = 1.0f / (float)max(e1 - e0, 1);
    g_agg16[hw * 16 + lane] = s * inv;
}

// ---------------- layer-1 transform: h1 = relu(agg16@Wl1^T + x@Wr1^T + b1) ----------------
__global__ __launch_bounds__(128) void l1_k(const float* __restrict__ x,
                                            const float* __restrict__ Wl1,
                                            const float* __restrict__ Wr1,
                                            const float* __restrict__ b1, int n) {
    __shared__ float4 sA[32 * 4];
    __shared__ float4 sX[32 * 4];
    int o = threadIdx.x;           // 0..127 output channel
    int nb = blockIdx.x * 32;
    float wl[16], wr[16];
#pragma unroll
    for (int k = 0; k < 16; k++) { wl[k] = Wl1[o * 16 + k]; wr[k] = Wr1[o * 16 + k]; }
    float bb = b1[o];
    int cnt = min(32, n - nb);
    for (int i = o; i < cnt * 4; i += 128) {
        sA[i] = ((const float4*)g_agg16)[nb * 4 + i];
        sX[i] = ((const float4*)x)[nb * 4 + i];
    }
    __syncthreads();
    for (int nn = 0; nn < cnt; nn++) {
        float acc = bb;
#pragma unroll
        for (int q = 0; q < 4; q++) {
            float4 a = sA[nn * 4 + q];
            float4 xx = sX[nn * 4 + q];
            acc += a.x  * wl[q * 4 + 0] + a.y  * wl[q * 4 + 1]
                 + a.z  * wl[q * 4 + 2] + a.w  * wl[q * 4 + 3];
            acc += xx.x * wr[q * 4 + 0] + xx.y * wr[q * 4 + 1]
                 + xx.z * wr[q * 4 + 2] + xx.w * wr[q * 4 + 3];
        }
        g_h1[(nb + nn) * 128 + o] = fmaxf(acc, 0.f);
    }
}

// ---------------- 128-dim aggregation: mean over in-neighbors (warp per node) ----------------
__global__ __launch_bounds__(256) void agg128_k(int which, int n) {
    const float* __restrict__ h = (which == 1) ? g_h1 : g_h2;
    int w = (blockIdx.x * blockDim.x + threadIdx.x) >> 5;
    if (w >= n) return;
    int lane = threadIdx.x & 31;
    int f = lane * 4;
    int e0 = g_off[w], e1 = g_off[w + 1];
    float4 s = make_float4(0.f, 0.f, 0.f, 0.f);
    int e = e0;
    for (; e + 1 < e1; e += 2) {
        int s0 = g_srcl[e];
        int s1 = g_srcl[e + 1];
        float4 v0 = *(const float4*)(h + (size_t)s0 * 128 + f);
        float4 v1 = *(const float4*)(h + (size_t)s1 * 128 + f);
        s.x += v0.x + v1.x; s.y += v0.y + v1.y;
        s.z += v0.z + v1.z; s.w += v0.w + v1.w;
    }
    if (e < e1) {
        int s0 = g_srcl[e];
        float4 v0 = *(const float4*)(h + (size_t)s0 * 128 + f);
        s.x += v0.x; s.y += v0.y; s.z += v0.z; s.w += v0.w;
    }
    float inv = 1.0f / (float)max(e1 - e0, 1);
    s.x *= inv; s.y *= inv; s.z *= inv; s.w *= inv;
    *(float4*)(g_agg + (size_t)w * 128 + f) = s;
}

// ---------------- GEMM: hout = relu([agg|hprev] @ U + b), fp32x2 ----------------
// Tile: 64 nodes x 128 outputs, 128 threads, thread = 8 nodes x 8 outputs.
// 782 blocks, target occ 5 -> ~single wave on 148 SMs.
__global__ __launch_bounds__(128, 5) void gemm_k(int layer, const float* __restrict__ bias, int n) {
    __shared__ float As[64 * 36];      // [node][k], pad 36 for 16B-aligned stores
    __shared__ float Bs[32 * 128];     // [k][o]
    const float* __restrict__ hprev = (layer == 2) ? g_h1 : g_h2;
    float* __restrict__ hout        = (layer == 2) ? g_h2 : g_h1;
    const float* __restrict__ U     = g_U + (layer - 2) * (256 * 128);

    int tid = threadIdx.x;
    int tx = tid & 15;        // output group: o0 = tx*8
    int ty = tid >> 4;        // node group (0..7): n0 = ty*8
    int nb = blockIdx.x * 64;
    int o0 = tx * 8;

    unsigned long long acc[8][4];
#pragma unroll
    for (int i = 0; i < 8; i++)
#pragma unroll
        for (int j = 0; j < 4; j++) acc[i][j] = 0ull;

    for (int kb = 0; kb < 256; kb += 32) {
        const float* src = (kb < 128) ? (g_agg + kb) : (hprev + (kb - 128));
        // stage A: 64 nodes x 32 k = 512 float4
#pragma unroll
        for (int r = 0; r < 4; r++) {
            int lf = tid + r * 128;
            int nnn = lf >> 3;
            int kq = lf & 7;
            int gn = nb + nnn;
            float4 v;
            if (gn < n) v = *(const float4*)(src + (size_t)gn * 128 + kq * 4);
            else        v = make_float4(0.f, 0.f, 0.f, 0.f);
            *(float4*)&As[nnn * 36 + kq * 4] = v;
        }
        // stage B: 32 k x 128 o = 1024 float4
#pragma unroll
        for (int r = 0; r < 8; r++) {
            int lf = tid + r * 128;
            int k = lf >> 5;
            int oq = lf & 31;
            *(float4*)&Bs[k * 128 + oq * 4] = *(const float4*)(U + (size_t)(kb + k) * 128 + oq * 4);
        }
        __syncthreads();
#pragma unroll 4
        for (int k = 0; k < 32; k++) {
            ulonglong2 w0 = *(const ulonglong2*)&Bs[k * 128 + o0];       // o0..o0+3
            ulonglong2 w1 = *(const ulonglong2*)&Bs[k * 128 + o0 + 4];   // o0+4..o0+7
#pragma unroll
            for (int i2 = 0; i2 < 8; i2++) {
                float a = As[(ty * 8 + i2) * 36 + k];
                unsigned long long aa = pack2f(a, a);
                acc[i2][0] = ffma2(aa, w0.x, acc[i2][0]);
                acc[i2][1] = ffma2(aa, w0.y, acc[i2][1]);
                acc[i2][2] = ffma2(aa, w1.x, acc[i2][2]);
                acc[i2][3] = ffma2(aa, w1.y, acc[i2][3]);
            }
        }
        __syncthreads();
    }

    float bv[8];
    *(float4*)&bv[0] = *(const float4*)(bias + o0);
    *(float4*)&bv[4] = *(const float4*)(bias + o0 + 4);
#pragma unroll
    for (int i2 = 0; i2 < 8; i2++) {
        int gn = nb + ty * 8 + i2;
        if (gn < n) {
            float r[8];
#pragma unroll
            for (int j = 0; j < 4; j++) unpack2f(acc[i2][j], r[2 * j], r[2 * j + 1]);
#pragma unroll
            for (int j = 0; j < 8; j++) r[j] = fmaxf(r[j] + bv[j], 0.f);
            float* dst = hout + (size_t)gn * 128 + o0;
            *(float4*)dst = make_float4(r[0], r[1], r[2], r[3]);
            *(float4*)(dst + 4) = make_float4(r[4], r[5], r[6], r[7]);
        }
    }
}

// ---------------- head: out = h3 @ Wh^T + bh ----------------
__global__ __launch_bounds__(128) void head_k(const float* __restrict__ Wh,
                                              const float* __restrict__ bh,
                                              float* __restrict__ out, int n) {
    int w = (blockIdx.x * blockDim.x + threadIdx.x) >> 5;
    if (w >= n) return;
    int lane = threadIdx.x & 31;
    float4 hv = *(const float4*)(g_h1 + (size_t)w * 128 + lane * 4);   // layer3 out in g_h1
#pragma unroll
    for (int o = 0; o < 4; o++) {
        float4 wv = *(const float4*)(Wh + o * 128 + lane * 4);
        float p = hv.x * wv.x + hv.y * wv.y + hv.z * wv.z + hv.w * wv.w;
#pragma unroll
        for (int ofs = 16; ofs; ofs >>= 1) p += __shfl_down_sync(0xffffffffu, p, ofs);
        if (lane == 0) out[w * 4 + o] = p + bh[o];
    }
}

// ---------------- host ----------------
extern "C" void kernel_launch(void* const* d_in, const int* in_sizes, int n_in,
                              void* d_out, int out_size) {
    const float* x   = (const float*)d_in[0];
    const void*  ei  = d_in[1];
    const float* Wl1 = (const float*)d_in[2];
    const float* Wr1 = (const float*)d_in[3];
    const float* b1  = (const float*)d_in[4];
    const float* Wl2 = (const float*)d_in[5];
    const float* Wr2 = (const float*)d_in[6];
    const float* b2  = (const float*)d_in[7];
    const float* Wl3 = (const float*)d_in[8];
    const float* Wr3 = (const float*)d_in[9];
    const float* b3  = (const float*)d_in[10];
    const float* Wh  = (const float*)d_in[11];
    const float* bh  = (const float*)d_in[12];
    float* out = (float*)d_out;

    int n = in_sizes[0] / 16;      // 50000
    int e = in_sizes[1] / 2;       // 600000
    if (n > NN) n = NN;
    if (e > NE) e = NE;

    int gb_e = (e + 255) / 256;
    int gb_n = (n + 255) / 256;
    int nsb  = (n + 1023) / 1024;  // scan blocks (<= 64)

    // CSR build
    init_k<<<gb_n, 256>>>(ei, n);
    count_k<<<gb_e, 256>>>(ei, e);
    partscan_k<<<nsb, 1024>>>(n);
    bscan_k<<<1, 64>>>(nsb, n);
    addoff_k<<<gb_n, 256>>>(n);
    fill_k<<<gb_e, 256>>>(ei, e);

    // weight prep for layers 2,3
    prepU_k<<<256, 256>>>(Wl2, Wr2, Wl3, Wr3);

    // layer 1
    agg16_k<<<(n + 15) / 16, 256>>>(x, n);
    l1_k<<<(n + 31) / 32, 128>>>(x, Wl1, Wr1, b1, n);

    // layer 2
    agg128_k<<<(n + 7) / 8, 256>>>(1, n);
    gemm_k<<<(n + 63) / 64, 128>>>(2, b2, n);

    // layer 3
    agg128_k<<<(n + 7) / 8, 256>>>(2, n);
    gemm_k<<<(n + 63) / 64, 128>>>(3, b3, n);

    // head
    head_k<<<(n + 3) / 4, 128>>>(Wh, bh, out, n);
}

// round 7
// speedup vs baseline: 1.3685x; 1.3685x over previous
#include <cuda_runtime.h>
#include <cstdint>

// ---------------------------------------------------------------------------
// GraphSAGE (3x SAGEConv mean + linear head), N=50000, E=600000, 16->128->128->128->4
//   R6: R4's multi-block scan + float4 l1 + half-warp agg16, with GEMM reverted
//       to the R3 shape (128x128 tile, 256 threads, occ 2 -> no register spills).
// ---------------------------------------------------------------------------

#define NN 50000
#define NE 600000

__device__ int   g_is64;
__device__ int   g_deg[NN];
__device__ int   g_off[NN + 1];
__device__ int   g_cur[NN];
__device__ int   g_bsum[64];
__device__ int   g_boff[64];
__device__ int   g_srcl[NE];
__device__ __align__(16) float g_agg16[NN * 16];
__device__ __align__(16) float g_agg[NN * 128];
__device__ __align__(16) float g_h1[NN * 128];
__device__ __align__(16) float g_h2[NN * 128];
__device__ __align__(16) float g_U[2 * 256 * 128];   // k-major [Wl|Wr] for layers 2,3

// ---------------- fp32x2 helpers ----------------
__device__ __forceinline__ unsigned long long pack2f(float a, float b) {
    unsigned long long r;
    asm("mov.b64 %0, {%1, %2};" : "=l"(r) : "f"(a), "f"(b));
    return r;
}
__device__ __forceinline__ void unpack2f(unsigned long long v, float& a, float& b) {
    asm("mov.b64 {%0, %1}, %2;" : "=f"(a), "=f"(b) : "l"(v));
}
__device__ __forceinline__ unsigned long long ffma2(unsigned long long a,
                                                    unsigned long long b,
                                                    unsigned long long c) {
    unsigned long long d;
    asm("fma.rn.f32x2 %0, %1, %2, %3;" : "=l"(d) : "l"(a), "l"(b), "l"(c));
    return d;
}

__device__ __forceinline__ int edge_val(const void* ei, long long idx, int is64) {
    if (is64) return (int)((const long long*)ei)[idx];
    return ((const int*)ei)[idx];
}

// ---------------- init: zero degrees + detect edge dtype ----------------
__global__ void init_k(const void* ei, int n) {
    int i = blockIdx.x * blockDim.x + threadIdx.x;
    if (i < n) g_deg[i] = 0;
    if (i == 0) {
        const int* p = (const int*)ei;
        int acc = 0;
        for (int j = 1; j < 256; j += 2) acc |= p[j];
        g_is64 = (acc == 0) ? 1 : 0;
    }
}

__global__ void count_k(const void* ei, int e) {
    int i = blockIdx.x * blockDim.x + threadIdx.x;
    if (i >= e) return;
    int is64 = g_is64;
    int d = edge_val(ei, (long long)e + i, is64);
    atomicAdd(&g_deg[d], 1);
}

// ---------------- multi-block exclusive scan of g_deg -> g_off ----------------
__global__ __launch_bounds__(1024) void partscan_k(int n) {
    __shared__ int wsum[32];
    int tid = threadIdx.x, lane = tid & 31, wid = tid >> 5;
    int i = blockIdx.x * 1024 + tid;
    int v = (i < n) ? g_deg[i] : 0;
    int xv = v;
#pragma unroll
    for (int o = 1; o < 32; o <<= 1) {
        int y = __shfl_up_sync(0xffffffffu, xv, o);
        if (lane >= o) xv += y;
    }
    if (lane == 31) wsum[wid] = xv;
    __syncthreads();
    if (wid == 0) {
        int wv = wsum[lane];
        int xw = wv;
#pragma unroll
        for (int o = 1; o < 32; o <<= 1) {
            int y = __shfl_up_sync(0xffffffffu, xw, o);
            if (lane >= o) xw += y;
        }
        wsum[lane] = xw - wv;   // exclusive warp offsets
    }
    __syncthreads();
    int incl = xv + wsum[wid];
    if (i < n) g_off[i] = incl - v;            // block-local exclusive
    if (tid == 1023) g_bsum[blockIdx.x] = incl;
}

__global__ void bscan_k(int nb, int n) {       // 1 block, 64 threads
    __shared__ int ws[2];
    int t = threadIdx.x, lane = t & 31, w = t >> 5;
    int v = (t < nb) ? g_bsum[t] : 0;
    int x = v;
#pragma unroll
    for (int o = 1; o < 32; o <<= 1) {
        int y = __shfl_up_sync(0xffffffffu, x, o);
        if (lane >= o) x += y;
    }
    if (lane == 31) ws[w] = x;
    __syncthreads();
    if (w == 1) x += ws[0];
    g_boff[t] = x - v;                         // exclusive block offsets
    if (t == 63) g_off[n] = x;                 // grand total
}

__global__ void addoff_k(int n) {
    int i = blockIdx.x * blockDim.x + threadIdx.x;
    if (i < n) {
        int o = g_off[i] + g_boff[i >> 10];
        g_off[i] = o;
        g_cur[i] = o;
    }
}

__global__ void fill_k(const void* ei, int e) {
    int i = blockIdx.x * blockDim.x + threadIdx.x;
    if (i >= e) return;
    int is64 = g_is64;
    int s = edge_val(ei, i, is64);
    int d = edge_val(ei, (long long)e + i, is64);
    int p = atomicAdd(&g_cur[d], 1);
    g_srcl[p] = s;
}

// ---------------- weight prep: U[k][o] = k<128 ? Wl[o][k] : Wr[o][k-128] ----------------
__global__ void prepU_k(const float* __restrict__ Wl2, const float* __restrict__ Wr2,
                        const float* __restrict__ Wl3, const float* __restrict__ Wr3) {
    int idx = blockIdx.x * blockDim.x + threadIdx.x;   // 0 .. 65535
    int layer = idx >> 15;
    int r = idx & 32767;
    int k = r >> 7;
    int o = r & 127;
    const float* Wl = layer ? Wl3 : Wl2;
    const float* Wr = layer ? Wr3 : Wr2;
    float v = (k < 128) ? Wl[o * 128 + k] : Wr[o * 128 + (k - 128)];
    g_U[layer * 32768 + k * 128 + o] = v;
}

// ---------------- layer-1 aggregation: half-warp per node (16-dim mean) ----------------
__global__ __launch_bounds__(256) void agg16_k(const float* __restrict__ x, int n) {
    int hw = (blockIdx.x * blockDim.x + threadIdx.x) >> 4;   // half-warp = node
    if (hw >= n) return;
    int lane = threadIdx.x & 15;
    int e0 = g_off[hw], e1 = g_off[hw + 1];
    float s = 0.f;
    int e = e0;
    for (; e + 1 < e1; e += 2) {
        int s0 = g_srcl[e], s1 = g_srcl[e + 1];
        s += x[s0 * 16 + lane] + x[s1 * 16 + lane];
    }
    if (e < e1) s += x[g_srcl[e] * 16 + lane];
    float inv = 1.0f / (float)max(e1 - e0, 1);
    g_agg16[hw * 16 + lane] = s * inv;
}

// ---------------- layer-1 transform: h1 = relu(agg16@Wl1^T + x@Wr1^T + b1) ----------------
__global__ __launch_bounds__(128) void l1_k(const float* __restrict__ x,
                                            const float* __restrict__ Wl1,
                                            const float* __restrict__ Wr1,
                                            const float* __restrict__ b1, int n) {
    __shared__ float4 sA[32 * 4];
    __shared__ float4 sX[32 * 4];
    int o = threadIdx.x;           // 0..127 output channel
    int nb = blockIdx.x * 32;
    float wl[16], wr[16];
#pragma unroll
    for (int k = 0; k < 16; k++) { wl[k] = Wl1[o * 16 + k]; wr[k] = Wr1[o * 16 + k]; }
    float bb = b1[o];
    int cnt = min(32, n - nb);
    for (int i = o; i < cnt * 4; i += 128) {
        sA[i] = ((const float4*)g_agg16)[nb * 4 + i];
        sX[i] = ((const float4*)x)[nb * 4 + i];
    }
    __syncthreads();
    for (int nn = 0; nn < cnt; nn++) {
        float acc = bb;
#pragma unroll
        for (int q = 0; q < 4; q++) {
            float4 a = sA[nn * 4 + q];
            float4 xx = sX[nn * 4 + q];
            acc += a.x  * wl[q * 4 + 0] + a.y  * wl[q * 4 + 1]
                 + a.z  * wl[q * 4 + 2] + a.w  * wl[q * 4 + 3];
            acc += xx.x * wr[q * 4 + 0] + xx.y * wr[q * 4 + 1]
                 + xx.z * wr[q * 4 + 2] + xx.w * wr[q * 4 + 3];
        }
        g_h1[(nb + nn) * 128 + o] = fmaxf(acc, 0.f);
    }
}

// ---------------- 128-dim aggregation: mean over in-neighbors (warp per node) ----------------
__global__ __launch_bounds__(256) void agg128_k(int which, int n) {
    const float* __restrict__ h = (which == 1) ? g_h1 : g_h2;
    int w = (blockIdx.x * blockDim.x + threadIdx.x) >> 5;
    if (w >= n) return;
    int lane = threadIdx.x & 31;
    int f = lane * 4;
    int e0 = g_off[w], e1 = g_off[w + 1];
    float4 s = make_float4(0.f, 0.f, 0.f, 0.f);
    int e = e0;
    for (; e + 1 < e1; e += 2) {
        int s0 = g_srcl[e];
        int s1 = g_srcl[e + 1];
        float4 v0 = *(const float4*)(h + (size_t)s0 * 128 + f);
        float4 v1 = *(const float4*)(h + (size_t)s1 * 128 + f);
        s.x += v0.x + v1.x; s.y += v0.y + v1.y;
        s.z += v0.z + v1.z; s.w += v0.w + v1.w;
    }
    if (e < e1) {
        int s0 = g_srcl[e];
        float4 v0 = *(const float4*)(h + (size_t)s0 * 128 + f);
        s.x += v0.x; s.y += v0.y; s.z += v0.z; s.w += v0.w;
    }
    float inv = 1.0f / (float)max(e1 - e0, 1);
    s.x *= inv; s.y *= inv; s.z *= inv; s.w *= inv;
    *(float4*)(g_agg + (size_t)w * 128 + f) = s;
}

// ---------------- GEMM: hout = relu([agg|hprev] @ U + b), fp32x2 ----------------
// R3 shape: 128 nodes x 128 outputs per block, 256 threads, thread = 8n x 8o.
// No reg cap beyond occ 2 (~128 regs available) -> accumulators stay in regs.
__global__ __launch_bounds__(256, 2) void gemm_k(int layer, const float* __restrict__ bias, int n) {
    __shared__ float As[128 * 36];     // [node][k] pad 36 (16B-aligned float4 stores)
    __shared__ float Bs[32 * 128];     // [k][o]
    const float* __restrict__ hprev = (layer == 2) ? g_h1 : g_h2;
    float* __restrict__ hout        = (layer == 2) ? g_h2 : g_h1;
    const float* __restrict__ U     = g_U + (layer - 2) * (256 * 128);

    int tid = threadIdx.x;
    int tx = tid & 15;        // output group: o0 = tx*8
    int ty = tid >> 4;        // node group:  n0 = ty*8
    int nb = blockIdx.x * 128;
    int o0 = tx * 8;

    unsigned long long acc[8][4];
#pragma unroll
    for (int i = 0; i < 8; i++)
#pragma unroll
        for (int j = 0; j < 4; j++) acc[i][j] = 0ull;

    for (int kb = 0; kb < 256; kb += 32) {
        const float* src = (kb < 128) ? (g_agg + kb) : (hprev + (kb - 128));
        // stage A: 128 nodes x 32 k
#pragma unroll
        for (int r = 0; r < 4; r++) {
            int lf = tid + r * 256;        // 0..1023 float4s
            int nnn = lf >> 3;
            int kq = lf & 7;
            int gn = nb + nnn;
            float4 v;
            if (gn < n) v = *(const float4*)(src + (size_t)gn * 128 + kq * 4);
            else        v = make_float4(0.f, 0.f, 0.f, 0.f);
            *(float4*)&As[nnn * 36 + kq * 4] = v;
        }
        // stage B: 32 k x 128 o
#pragma unroll
        for (int r = 0; r < 4; r++) {
            int lf = tid + r * 256;
            int k = lf >> 5;
            int oq = lf & 31;
            *(float4*)&Bs[k * 128 + oq * 4] = *(const float4*)(U + (size_t)(kb + k) * 128 + oq * 4);
        }
        __syncthreads();
#pragma unroll 4
        for (int k = 0; k < 32; k++) {
            ulonglong2 w0 = *(const ulonglong2*)&Bs[k * 128 + o0];       // outputs o0..o0+3
            ulonglong2 w1 = *(const ulonglong2*)&Bs[k * 128 + o0 + 4];   // outputs o0+4..o0+7
#pragma unroll
            for (int i2 = 0; i2 < 8; i2++) {
                float a = As[(ty * 8 + i2) * 36 + k];
                unsigned long long aa = pack2f(a, a);
                acc[i2][0] = ffma2(aa, w0.x, acc[i2][0]);
                acc[i2][1] = ffma2(aa, w0.y, acc[i2][1]);
                acc[i2][2] = ffma2(aa, w1.x, acc[i2][2]);
                acc[i2][3] = ffma2(aa, w1.y, acc[i2][3]);
            }
        }
        __syncthreads();
    }

    float bv[8];
    *(float4*)&bv[0] = *(const float4*)(bias + o0);
    *(float4*)&bv[4] = *(const float4*)(bias + o0 + 4);
#pragma unroll
    for (int i2 = 0; i2 < 8; i2++) {
        int gn = nb + ty * 8 + i2;
        if (gn < n) {
            float r[8];
#pragma unroll
            for (int j = 0; j < 4; j++) unpack2f(acc[i2][j], r[2 * j], r[2 * j + 1]);
#pragma unroll
            for (int j = 0; j < 8; j++) r[j] = fmaxf(r[j] + bv[j], 0.f);
            float* dst = hout + (size_t)gn * 128 + o0;
            *(float4*)dst = make_float4(r[0], r[1], r[2], r[3]);
            *(float4*)(dst + 4) = make_float4(r[4], r[5], r[6], r[7]);
        }
    }
}

// ---------------- head: out = h3 @ Wh^T + bh ----------------
__global__ __launch_bounds__(128) void head_k(const float* __restrict__ Wh,
                                              const float* __restrict__ bh,
                                              float* __restrict__ out, int n) {
    int w = (blockIdx.x * blockDim.x + threadIdx.x) >> 5;
    if (w >= n) return;
    int lane = threadIdx.x & 31;
    float4 hv = *(const float4*)(g_h1 + (size_t)w * 128 + lane * 4);   // layer3 out in g_h1
#pragma unroll
    for (int o = 0; o < 4; o++) {
        float4 wv = *(const float4*)(Wh + o * 128 + lane * 4);
        float p = hv.x * wv.x + hv.y * wv.y + hv.z * wv.z + hv.w * wv.w;
#pragma unroll
        for (int ofs = 16; ofs; ofs >>= 1) p += __shfl_down_sync(0xffffffffu, p, ofs);
        if (lane == 0) out[w * 4 + o] = p + bh[o];
    }
}

// ---------------- host ----------------
extern "C" void kernel_launch(void* const* d_in, const int* in_sizes, int n_in,
                              void* d_out, int out_size) {
    const float* x   = (const float*)d_in[0];
    const void*  ei  = d_in[1];
    const float* Wl1 = (const float*)d_in[2];
    const float* Wr1 = (const float*)d_in[3];
    const float* b1  = (const float*)d_in[4];
    const float* Wl2 = (const float*)d_in[5];
    const float* Wr2 = (const float*)d_in[6];
    const float* b2  = (const float*)d_in[7];
    const float* Wl3 = (const float*)d_in[8];
    const float* Wr3 = (const float*)d_in[9];
    const float* b3  = (const float*)d_in[10];
    const float* Wh  = (const float*)d_in[11];
    const float* bh  = (const float*)d_in[12];
    float* out = (float*)d_out;

    int n = in_sizes[0] / 16;      // 50000
    int e = in_sizes[1] / 2;       // 600000
    if (n > NN) n = NN;
    if (e > NE) e = NE;

    int gb_e = (e + 255) / 256;
    int gb_n = (n + 255) / 256;
    int nsb  = (n + 1023) / 1024;  // scan blocks (<= 64)

    // CSR build
    init_k<<<gb_n, 256>>>(ei, n);
    count_k<<<gb_e, 256>>>(ei, e);
    partscan_k<<<nsb, 1024>>>(n);
    bscan_k<<<1, 64>>>(nsb, n);
    addoff_k<<<gb_n, 256>>>(n);
    fill_k<<<gb_e, 256>>>(ei, e);

    // weight prep for layers 2,3
    prepU_k<<<256, 256>>>(Wl2, Wr2, Wl3, Wr3);

    // layer 1
    agg16_k<<<(n + 15) / 16, 256>>>(x, n);
    l1_k<<<(n + 31) / 32, 128>>>(x, Wl1, Wr1, b1, n);

    // layer 2
    agg128_k<<<(n + 7) / 8, 256>>>(1, n);
    gemm_k<<<(n + 127) / 128, 256>>>(2, b2, n);

    // layer 3
    agg128_k<<<(n + 7) / 8, 256>>>(2, n);
    gemm_k<<<(n + 127) / 128, 256>>>(3, b3, n);

    // head
    head_k<<<(n + 3) / 4, 128>>>(Wh, bh, out, n);
}